// round 6
// baseline (speedup 1.0000x reference)
#include <cuda_runtime.h>
#include <cstdint>

#define N_NODESC 100000
#define N_EDGESC 2500000
#define IN_CH 32
#define HID 16
#define OUT_CH 64
#define NUM_GRAPHS 64

// ---------------- scratch ----------------
__device__ __align__(16) float g_y[N_NODESC * HID];    // x @ w1_l^T
__device__ __align__(16) float g_xr[N_NODESC * HID];   // x @ w1_r^T
__device__ __align__(16) float g_h1[N_NODESC * HID];   // layer-1 output
__device__ __align__(16) float g_m2[N_NODESC * HID];   // layer-2 mean aggregate
__device__ __align__(16) float g_gacc[NUM_GRAPHS * OUT_CH];
__device__ __align__(16) float g_gcnt[NUM_GRAPHS];
__device__ __align__(16) int g_deg[N_NODESC];          // zero at steady state (re-zeroed by kLayer2)
__device__ __align__(16) int g_start[N_NODESC];
__device__ __align__(16) int g_cursor[N_NODESC];
__device__ int g_csr[N_EDGESC];                        // src ids grouped by dst

__device__ __forceinline__ void red_add_v4(float* p, float a, float b, float c, float d) {
    asm volatile("red.global.add.v4.f32 [%0], {%1, %2, %3, %4};"
                 :: "l"(p), "f"(a), "f"(b), "f"(c), "f"(d) : "memory");
}

// ---------------- Kernel 1: fused node pre-transform + edge degree count ----------------
// grid covers all edges; first N_NODES threads also do the node GEMV.
__global__ void __launch_bounds__(256) kPreDeg(const float* __restrict__ x,
                                               const float* __restrict__ w1l,
                                               const float* __restrict__ w1r,
                                               const int* __restrict__ ei) {
    __shared__ __align__(16) float swl[HID * IN_CH];
    __shared__ __align__(16) float swr[HID * IN_CH];
    int t = threadIdx.x;
    int idx = blockIdx.x * blockDim.x + t;

    // edge part: degree count (g_deg is all-zero on entry)
    if (idx < N_EDGESC)
        atomicAdd(&g_deg[__ldg(&ei[N_EDGESC + idx])], 1);

    // node part: only blocks that own node indices
    if (blockIdx.x * blockDim.x < N_NODESC) {
        for (int i = t; i < HID * IN_CH; i += blockDim.x) {
            swl[i] = w1l[i];
            swr[i] = w1r[i];
        }
        __syncthreads();

        int n = idx;
        if (n < N_NODESC) {
            if (n < NUM_GRAPHS * OUT_CH) g_gacc[n] = 0.0f;
            if (n < NUM_GRAPHS) g_gcnt[n] = 0.0f;

            float xv[IN_CH];
            const float4* xp = reinterpret_cast<const float4*>(x + (size_t)n * IN_CH);
#pragma unroll
            for (int i = 0; i < IN_CH / 4; i++) {
                float4 v = __ldg(xp + i);
                xv[4*i+0] = v.x; xv[4*i+1] = v.y; xv[4*i+2] = v.z; xv[4*i+3] = v.w;
            }

            float yl[HID], yr[HID];
#pragma unroll
            for (int o = 0; o < HID; o++) {
                float al = 0.0f, ar = 0.0f;
#pragma unroll
                for (int kk = 0; kk < IN_CH / 4; kk++) {
                    float4 wl = *reinterpret_cast<float4*>(&swl[o * IN_CH + kk * 4]);
                    float4 wr = *reinterpret_cast<float4*>(&swr[o * IN_CH + kk * 4]);
                    al += xv[kk*4+0]*wl.x + xv[kk*4+1]*wl.y + xv[kk*4+2]*wl.z + xv[kk*4+3]*wl.w;
                    ar += xv[kk*4+0]*wr.x + xv[kk*4+1]*wr.y + xv[kk*4+2]*wr.z + xv[kk*4+3]*wr.w;
                }
                yl[o] = al; yr[o] = ar;
            }

            float4* yp = reinterpret_cast<float4*>(g_y  + (size_t)n * HID);
            float4* rp = reinterpret_cast<float4*>(g_xr + (size_t)n * HID);
#pragma unroll
            for (int i = 0; i < HID / 4; i++) {
                yp[i] = make_float4(yl[4*i], yl[4*i+1], yl[4*i+2], yl[4*i+3]);
                rp[i] = make_float4(yr[4*i], yr[4*i+1], yr[4*i+2], yr[4*i+3]);
            }
        }
    }
}

// ---------------- Kernel 2: single-block exclusive scan of degrees ----------------
#define N4 (N_NODESC / 4)          // 25000, exact
__global__ void __launch_bounds__(1024) kScanAll() {
    __shared__ int warpsum[32];
    int t = threadIdx.x;
    int lane = t & 31, wid = t >> 5;
    int carry = 0;

    const int4* deg4 = reinterpret_cast<const int4*>(g_deg);
    int4* start4  = reinterpret_cast<int4*>(g_start);
    int4* cursor4 = reinterpret_cast<int4*>(g_cursor);

    const int ITER = (N4 + 1023) / 1024;   // 25
    for (int it = 0; it < ITER; it++) {
        int i4 = it * 1024 + t;
        int4 d = (i4 < N4) ? deg4[i4] : make_int4(0, 0, 0, 0);
        int v = d.x + d.y + d.z + d.w;

        // inclusive warp scan of v
        int xacc = v;
#pragma unroll
        for (int off = 1; off < 32; off <<= 1) {
            int y = __shfl_up_sync(0xffffffffu, xacc, off);
            if (lane >= off) xacc += y;
        }
        if (lane == 31) warpsum[wid] = xacc;
        __syncthreads();
        if (wid == 0) {
            int w = warpsum[lane];
#pragma unroll
            for (int off = 1; off < 32; off <<= 1) {
                int y = __shfl_up_sync(0xffffffffu, w, off);
                if (lane >= off) w += y;
            }
            warpsum[lane] = w;     // inclusive over warps
        }
        __syncthreads();
        int warpoff = (wid == 0) ? 0 : warpsum[wid - 1];
        int total = warpsum[31];
        int base = carry + warpoff + (xacc - v);   // exclusive prefix of this thread's group

        if (i4 < N4) {
            int4 s;
            s.x = base;
            s.y = base + d.x;
            s.z = s.y + d.y;
            s.w = s.z + d.z;
            start4[i4] = s;
            cursor4[i4] = s;
        }
        carry += total;
        __syncthreads();   // protect warpsum before next iteration
    }
}

// ---------------- Kernel 3: CSR placement ----------------
__global__ void __launch_bounds__(256) kPlace(const int* __restrict__ ei) {
    int e = blockIdx.x * blockDim.x + threadIdx.x;
    if (e >= N_EDGESC) return;
    int s = __ldg(&ei[e]);
    int d = __ldg(&ei[N_EDGESC + e]);
    int pos = atomicAdd(&g_cursor[d], 1);
    g_csr[pos] = s;
}

// ---------------- Kernel 4/5: aggregation, warp per node, quad per edge ----------------
// MODE 0: h1 = relu(mean(y) + b1 + xr);  MODE 1: m2 = mean(h1)
template <int MODE>
__global__ void __launch_bounds__(256) kAgg(const float* __restrict__ val,
                                            const float* __restrict__ b1,
                                            float* __restrict__ outp) {
    int warp = (blockIdx.x * blockDim.x + threadIdx.x) >> 5;
    if (warp >= N_NODESC) return;
    int lane = threadIdx.x & 31;
    int c = lane & 3;          // 16B chunk within 64B row
    int eoff = lane >> 2;      // edge slot within batch of 8

    int start = __ldg(&g_start[warp]);
    int deg   = __ldg(&g_deg[warp]);

    float4 acc = make_float4(0.f, 0.f, 0.f, 0.f);
    for (int b = 0; b < deg; b += 8) {
        int el = b + eoff;
        bool ok = el < deg;
        int src = ok ? __ldg(&g_csr[start + el]) : 0;
        if (ok) {
            float4 v = __ldg(reinterpret_cast<const float4*>(val + (size_t)src * HID) + c);
            acc.x += v.x; acc.y += v.y; acc.z += v.z; acc.w += v.w;
        }
    }
#pragma unroll
    for (int st = 4; st <= 16; st <<= 1) {
        acc.x += __shfl_xor_sync(0xffffffffu, acc.x, st);
        acc.y += __shfl_xor_sync(0xffffffffu, acc.y, st);
        acc.z += __shfl_xor_sync(0xffffffffu, acc.z, st);
        acc.w += __shfl_xor_sync(0xffffffffu, acc.w, st);
    }

    if (lane < 4) {
        float inv = 1.0f / fmaxf((float)deg, 1.0f);
        float4 m = make_float4(acc.x * inv, acc.y * inv, acc.z * inv, acc.w * inv);
        if (MODE == 0) {
            float4 bb = __ldg(reinterpret_cast<const float4*>(b1) + c);
            float4 r  = *reinterpret_cast<const float4*>(&g_xr[(size_t)warp * HID + c * 4]);
            m.x = fmaxf(m.x + bb.x + r.x, 0.0f);
            m.y = fmaxf(m.y + bb.y + r.y, 0.0f);
            m.z = fmaxf(m.z + bb.z + r.z, 0.0f);
            m.w = fmaxf(m.w + bb.w + r.w, 0.0f);
        }
        *reinterpret_cast<float4*>(outp + (size_t)warp * HID + c * 4) = m;
    }
}

// ---------------- Kernel 6: node GEMV + warp-aggregated readout; re-zero g_deg ----------------
__global__ void __launch_bounds__(128) kLayer2(const int* __restrict__ batch,
                                               const float* __restrict__ w2l,
                                               const float* __restrict__ b2,
                                               const float* __restrict__ w2r) {
    __shared__ __align__(16) float swl[HID * OUT_CH];   // transposed [k][o]
    __shared__ __align__(16) float swr[HID * OUT_CH];
    __shared__ __align__(16) float sb2[OUT_CH];
    int t = threadIdx.x;
    for (int i = t; i < HID * OUT_CH; i += blockDim.x) {
        int o = i / HID, k = i % HID;
        swl[k * OUT_CH + o] = w2l[i];
        swr[k * OUT_CH + o] = w2r[i];
    }
    for (int i = t; i < OUT_CH; i += blockDim.x) sb2[i] = b2[i];
    __syncthreads();

    int n = blockIdx.x * blockDim.x + t;
    bool valid = n < N_NODESC;
    int nn = valid ? n : (N_NODESC - 1);
    int lane = t & 31;

    if (valid) g_deg[n] = 0;        // restore invariant for next invocation

    float av[HID], hv[HID];
    const float4* ap = reinterpret_cast<const float4*>(g_m2 + (size_t)nn * HID);
    const float4* hp = reinterpret_cast<const float4*>(g_h1 + (size_t)nn * HID);
#pragma unroll
    for (int i = 0; i < HID / 4; i++) {
        float4 a = ap[i];
        av[4*i] = a.x; av[4*i+1] = a.y; av[4*i+2] = a.z; av[4*i+3] = a.w;
        float4 h = hp[i];
        hv[4*i] = h.x; hv[4*i+1] = h.y; hv[4*i+2] = h.z; hv[4*i+3] = h.w;
    }

    float acc[OUT_CH];
#pragma unroll
    for (int o = 0; o < OUT_CH; o++) acc[o] = sb2[o];

#pragma unroll
    for (int k = 0; k < HID; k++) {
        float ak = av[k], hk = hv[k];
#pragma unroll
        for (int o = 0; o < OUT_CH; o += 4) {
            float4 wl = *reinterpret_cast<float4*>(&swl[k * OUT_CH + o]);
            float4 wr = *reinterpret_cast<float4*>(&swr[k * OUT_CH + o]);
            acc[o + 0] += ak * wl.x + hk * wr.x;
            acc[o + 1] += ak * wl.y + hk * wr.y;
            acc[o + 2] += ak * wl.z + hk * wr.z;
            acc[o + 3] += ak * wl.w + hk * wr.w;
        }
    }

    if (!valid) {
#pragma unroll
        for (int o = 0; o < OUT_CH; o++) acc[o] = 0.0f;
    }

    int g = __ldg(&batch[nn]);
    int g0 = __shfl_sync(0xffffffffu, g, 0);
    bool uni = __all_sync(0xffffffffu, g == g0);
    int nvalid = __popc(__ballot_sync(0xffffffffu, valid));

    if (uni) {
#pragma unroll
        for (int o = 0; o < OUT_CH; o++) {
            float v = acc[o];
            v += __shfl_xor_sync(0xffffffffu, v, 16);
            v += __shfl_xor_sync(0xffffffffu, v, 8);
            v += __shfl_xor_sync(0xffffffffu, v, 4);
            v += __shfl_xor_sync(0xffffffffu, v, 2);
            v += __shfl_xor_sync(0xffffffffu, v, 1);
            acc[o] = v;
        }
        if (lane == 0 && nvalid > 0) {
            float* gp = g_gacc + (size_t)g0 * OUT_CH;
#pragma unroll
            for (int o = 0; o < OUT_CH; o += 4)
                red_add_v4(gp + o, acc[o], acc[o + 1], acc[o + 2], acc[o + 3]);
            atomicAdd(&g_gcnt[g0], (float)nvalid);
        }
    } else if (valid) {
        float* gp = g_gacc + (size_t)g * OUT_CH;
#pragma unroll
        for (int o = 0; o < OUT_CH; o += 4)
            red_add_v4(gp + o, acc[o], acc[o + 1], acc[o + 2], acc[o + 3]);
        atomicAdd(&g_gcnt[g], 1.0f);
    }
}

// ---------------- Kernel 7: final divide ----------------
__global__ void __launch_bounds__(256) kFinal(float* __restrict__ out) {
    int i = blockIdx.x * blockDim.x + threadIdx.x;
    if (i >= NUM_GRAPHS * OUT_CH) return;
    out[i] = g_gacc[i] / fmaxf(g_gcnt[i >> 6], 1.0f);
}

// ---------------- launch ----------------
extern "C" void kernel_launch(void* const* d_in, const int* in_sizes, int n_in,
                              void* d_out, int out_size) {
    const float* x    = (const float*)d_in[0];
    const int*   ei   = (const int*)d_in[1];
    const int*   batch= (const int*)d_in[2];
    const float* w1l  = (const float*)d_in[3];
    const float* b1   = (const float*)d_in[4];
    const float* w1r  = (const float*)d_in[5];
    const float* w2l  = (const float*)d_in[6];
    const float* b2   = (const float*)d_in[7];
    const float* w2r  = (const float*)d_in[8];
    float* out = (float*)d_out;

    float* gy;  cudaGetSymbolAddress((void**)&gy,  g_y);
    float* gh1; cudaGetSymbolAddress((void**)&gh1, g_h1);
    float* gm2; cudaGetSymbolAddress((void**)&gm2, g_m2);

    const int TB = 256;
    int edgeBlocks = (N_EDGESC + TB - 1) / TB;
    int aggBlocks  = (N_NODESC * 32 + TB - 1) / TB;

    kPreDeg<<<edgeBlocks, TB>>>(x, w1l, w1r, ei);
    kScanAll<<<1, 1024>>>();
    kPlace<<<edgeBlocks, TB>>>(ei);
    kAgg<0><<<aggBlocks, TB>>>(gy, b1, gh1);
    kAgg<1><<<aggBlocks, TB>>>(gh1, b1, gm2);
    kLayer2<<<(N_NODESC + 127) / 128, 128>>>(batch, w2l, b2, w2r);
    kFinal<<<(NUM_GRAPHS * OUT_CH + TB - 1) / TB, TB>>>(out);
}

// round 7
// speedup vs baseline: 1.3486x; 1.3486x over previous
#include <cuda_runtime.h>
#include <cstdint>

#define N_NODESC 100000
#define N_EDGESC 2500000
#define IN_CH 32
#define HID 16
#define OUT_CH 64
#define NUM_GRAPHS 64

// ---------------- scratch ----------------
__device__ __align__(16) float g_y[N_NODESC * HID];     // x @ w1_l^T
__device__ __align__(16) float g_xr[N_NODESC * HID];    // x @ w1_r^T
__device__ __align__(16) float g_h1[N_NODESC * HID];    // layer-1 output
__device__ __align__(16) float g_agg1[N_NODESC * HID];
__device__ __align__(16) float g_agg2[N_NODESC * HID];
__device__ __align__(16) float g_cnt[N_NODESC];         // in-degree
__device__ __align__(16) float g_h1acc[NUM_GRAPHS * HID]; // per-graph sum of h1
__device__ __align__(16) float g_m2acc[NUM_GRAPHS * HID]; // per-graph sum of m2
__device__ __align__(16) float g_gcnt[NUM_GRAPHS];

__device__ __forceinline__ void red_add_v4(float* p, float a, float b, float c, float d) {
    asm volatile("red.global.add.v4.f32 [%0], {%1, %2, %3, %4};"
                 :: "l"(p), "f"(a), "f"(b), "f"(c), "f"(d) : "memory");
}

// ---------------- Kernel 1: pre-transform x -> y, xr; zero accumulators ----------------
__global__ void __launch_bounds__(256) kPre(const float* __restrict__ x,
                                            const float* __restrict__ w1l,
                                            const float* __restrict__ w1r) {
    __shared__ __align__(16) float swl[HID * IN_CH];
    __shared__ __align__(16) float swr[HID * IN_CH];
    int t = threadIdx.x;
    for (int i = t; i < HID * IN_CH; i += blockDim.x) {
        swl[i] = w1l[i];
        swr[i] = w1r[i];
    }
    __syncthreads();

    int n = blockIdx.x * blockDim.x + t;
    if (n >= N_NODESC) return;

    if (n < NUM_GRAPHS * HID) { g_h1acc[n] = 0.0f; g_m2acc[n] = 0.0f; }
    if (n < NUM_GRAPHS) g_gcnt[n] = 0.0f;

    float xv[IN_CH];
    const float4* xp = reinterpret_cast<const float4*>(x + (size_t)n * IN_CH);
#pragma unroll
    for (int i = 0; i < IN_CH / 4; i++) {
        float4 v = __ldg(xp + i);
        xv[4*i+0] = v.x; xv[4*i+1] = v.y; xv[4*i+2] = v.z; xv[4*i+3] = v.w;
    }

    float yl[HID], yr[HID];
#pragma unroll
    for (int o = 0; o < HID; o++) {
        float al = 0.0f, ar = 0.0f;
#pragma unroll
        for (int kk = 0; kk < IN_CH / 4; kk++) {
            float4 wl = *reinterpret_cast<float4*>(&swl[o * IN_CH + kk * 4]);
            float4 wr = *reinterpret_cast<float4*>(&swr[o * IN_CH + kk * 4]);
            al += xv[kk*4+0]*wl.x + xv[kk*4+1]*wl.y + xv[kk*4+2]*wl.z + xv[kk*4+3]*wl.w;
            ar += xv[kk*4+0]*wr.x + xv[kk*4+1]*wr.y + xv[kk*4+2]*wr.z + xv[kk*4+3]*wr.w;
        }
        yl[o] = al; yr[o] = ar;
    }

    float4* yp  = reinterpret_cast<float4*>(g_y  + (size_t)n * HID);
    float4* rp  = reinterpret_cast<float4*>(g_xr + (size_t)n * HID);
    float4* a1p = reinterpret_cast<float4*>(g_agg1 + (size_t)n * HID);
#pragma unroll
    for (int i = 0; i < HID / 4; i++) {
        yp[i] = make_float4(yl[4*i], yl[4*i+1], yl[4*i+2], yl[4*i+3]);
        rp[i] = make_float4(yr[4*i], yr[4*i+1], yr[4*i+2], yr[4*i+3]);
        a1p[i] = make_float4(0.f, 0.f, 0.f, 0.f);
    }
    g_cnt[n] = 0.0f;
}

// ---------------- Kernel 2/4: edge scatter, 4 threads/edge ----------------
template <int ADDCOUNT>
__global__ void __launch_bounds__(256) kScatter4(const int* __restrict__ ei,
                                                 const float* __restrict__ val,
                                                 float* __restrict__ acc) {
    int idx = blockIdx.x * blockDim.x + threadIdx.x;
    int e = idx >> 2;
    if (e >= N_EDGESC) return;
    int c = idx & 3;
    int s = __ldg(&ei[e]);
    int d = __ldg(&ei[N_EDGESC + e]);

    float4 v = __ldg(reinterpret_cast<const float4*>(val + (size_t)s * HID) + c);
    red_add_v4(acc + (size_t)d * HID + c * 4, v.x, v.y, v.z, v.w);
    if (ADDCOUNT && c == 0) atomicAdd(&g_cnt[d], 1.0f);
}

// ---------------- Kernel 3: h1 = relu(agg1/cnt + b1 + xr); zero agg2; h1 readout ----------------
__global__ void __launch_bounds__(256) kLayer1R(const float* __restrict__ b1,
                                                const int* __restrict__ batch) {
    int idx = blockIdx.x * blockDim.x + threadIdx.x;
    int n = idx >> 2;
    int c = idx & 3;
    bool valid = n < N_NODESC;
    int nn = valid ? n : (N_NODESC - 1);
    int lane = threadIdx.x & 31;

    float inv = 1.0f / fmaxf(g_cnt[nn], 1.0f);
    float4 a = *reinterpret_cast<float4*>(&g_agg1[(size_t)nn * HID + c * 4]);
    float4 r = *reinterpret_cast<float4*>(&g_xr[(size_t)nn * HID + c * 4]);
    float4 bb = __ldg(reinterpret_cast<const float4*>(b1) + c);

    float4 h;
    h.x = fmaxf(a.x * inv + bb.x + r.x, 0.0f);
    h.y = fmaxf(a.y * inv + bb.y + r.y, 0.0f);
    h.z = fmaxf(a.z * inv + bb.z + r.z, 0.0f);
    h.w = fmaxf(a.w * inv + bb.w + r.w, 0.0f);

    if (valid) {
        *reinterpret_cast<float4*>(&g_h1[(size_t)n * HID + c * 4]) = h;
        *reinterpret_cast<float4*>(&g_agg2[(size_t)n * HID + c * 4]) = make_float4(0.f, 0.f, 0.f, 0.f);
    } else {
        h = make_float4(0.f, 0.f, 0.f, 0.f);
    }

    // ---- per-graph readout of h1 ----
    int g = __ldg(&batch[nn]);
    int g0 = __shfl_sync(0xffffffffu, g, 0);
    bool uni = __all_sync(0xffffffffu, g == g0);
    int nval = __popc(__ballot_sync(0xffffffffu, valid && c == 0));   // valid nodes in warp

    if (uni) {
        // sum over the 8 nodes this warp covers (strides 4,8,16 keep chunk id c)
#pragma unroll
        for (int st = 4; st <= 16; st <<= 1) {
            h.x += __shfl_xor_sync(0xffffffffu, h.x, st);
            h.y += __shfl_xor_sync(0xffffffffu, h.y, st);
            h.z += __shfl_xor_sync(0xffffffffu, h.z, st);
            h.w += __shfl_xor_sync(0xffffffffu, h.w, st);
        }
        if (lane < 4)
            red_add_v4(&g_h1acc[(size_t)g0 * HID + lane * 4], h.x, h.y, h.z, h.w);
        if (lane == 0 && nval > 0) atomicAdd(&g_gcnt[g0], (float)nval);
    } else {
        if (valid) {
            red_add_v4(&g_h1acc[(size_t)g * HID + c * 4], h.x, h.y, h.z, h.w);
            if (c == 0) atomicAdd(&g_gcnt[g], 1.0f);
        }
    }
}

// ---------------- Kernel 5: m2 = agg2/cnt; per-graph readout of m2 (no per-node store) ----------------
__global__ void __launch_bounds__(256) kMean2R(const int* __restrict__ batch) {
    int idx = blockIdx.x * blockDim.x + threadIdx.x;
    int n = idx >> 2;
    int c = idx & 3;
    bool valid = n < N_NODESC;
    int nn = valid ? n : (N_NODESC - 1);
    int lane = threadIdx.x & 31;

    float inv = 1.0f / fmaxf(g_cnt[nn], 1.0f);
    float4 a = *reinterpret_cast<float4*>(&g_agg2[(size_t)nn * HID + c * 4]);
    float4 m = make_float4(a.x * inv, a.y * inv, a.z * inv, a.w * inv);
    if (!valid) m = make_float4(0.f, 0.f, 0.f, 0.f);

    int g = __ldg(&batch[nn]);
    int g0 = __shfl_sync(0xffffffffu, g, 0);
    bool uni = __all_sync(0xffffffffu, g == g0);

    if (uni) {
#pragma unroll
        for (int st = 4; st <= 16; st <<= 1) {
            m.x += __shfl_xor_sync(0xffffffffu, m.x, st);
            m.y += __shfl_xor_sync(0xffffffffu, m.y, st);
            m.z += __shfl_xor_sync(0xffffffffu, m.z, st);
            m.w += __shfl_xor_sync(0xffffffffu, m.w, st);
        }
        if (lane < 4)
            red_add_v4(&g_m2acc[(size_t)g0 * HID + lane * 4], m.x, m.y, m.z, m.w);
    } else {
        if (valid)
            red_add_v4(&g_m2acc[(size_t)g * HID + c * 4], m.x, m.y, m.z, m.w);
    }
}

// ---------------- Kernel 6: tiny output GEMM ----------------
// out[g,o] = (m2acc[g]/cnt) . w2l[o,:] + b2[o] + (h1acc[g]/cnt) . w2r[o,:]   (0 if cnt==0)
__global__ void __launch_bounds__(256) kFinal(const float* __restrict__ w2l,
                                              const float* __restrict__ b2,
                                              const float* __restrict__ w2r,
                                              float* __restrict__ out) {
    int i = blockIdx.x * blockDim.x + threadIdx.x;
    if (i >= NUM_GRAPHS * OUT_CH) return;
    int g = i >> 6;
    int o = i & 63;

    float cnt = g_gcnt[g];
    if (cnt < 0.5f) { out[i] = 0.0f; return; }
    float inv = 1.0f / cnt;

    float sum = __ldg(&b2[o]);
#pragma unroll
    for (int k = 0; k < HID; k += 4) {
        float4 mm = *reinterpret_cast<const float4*>(&g_m2acc[g * HID + k]);
        float4 hh = *reinterpret_cast<const float4*>(&g_h1acc[g * HID + k]);
        float4 wl = __ldg(reinterpret_cast<const float4*>(w2l + o * HID + k));
        float4 wr = __ldg(reinterpret_cast<const float4*>(w2r + o * HID + k));
        sum += inv * (mm.x * wl.x + mm.y * wl.y + mm.z * wl.z + mm.w * wl.w
                    + hh.x * wr.x + hh.y * wr.y + hh.z * wr.z + hh.w * wr.w);
    }
    out[i] = sum;
}

// ---------------- launch ----------------
extern "C" void kernel_launch(void* const* d_in, const int* in_sizes, int n_in,
                              void* d_out, int out_size) {
    const float* x    = (const float*)d_in[0];
    const int*   ei   = (const int*)d_in[1];
    const int*   batch= (const int*)d_in[2];
    const float* w1l  = (const float*)d_in[3];
    const float* b1   = (const float*)d_in[4];
    const float* w1r  = (const float*)d_in[5];
    const float* w2l  = (const float*)d_in[6];
    const float* b2   = (const float*)d_in[7];
    const float* w2r  = (const float*)d_in[8];
    float* out = (float*)d_out;

    float* gy;  cudaGetSymbolAddress((void**)&gy,  g_y);
    float* gh1; cudaGetSymbolAddress((void**)&gh1, g_h1);
    float* ga1; cudaGetSymbolAddress((void**)&ga1, g_agg1);
    float* ga2; cudaGetSymbolAddress((void**)&ga2, g_agg2);

    const int TB = 256;
    int nodeBlocks = (N_NODESC + TB - 1) / TB;
    int quadBlocks = ((N_EDGESC * 4) + TB - 1) / TB;
    int chBlocks   = (N_NODESC * 4 + TB - 1) / TB;

    kPre<<<nodeBlocks, TB>>>(x, w1l, w1r);
    kScatter4<1><<<quadBlocks, TB>>>(ei, gy, ga1);
    kLayer1R<<<chBlocks, TB>>>(b1, batch);
    kScatter4<0><<<quadBlocks, TB>>>(ei, gh1, ga2);
    kMean2R<<<chBlocks, TB>>>(batch);
    kFinal<<<(NUM_GRAPHS * OUT_CH + TB - 1) / TB, TB>>>(w2l, b2, w2r, out);
}

// round 8
// speedup vs baseline: 1.8003x; 1.3349x over previous
#include <cuda_runtime.h>
#include <cuda_fp16.h>
#include <cstdint>

#define N_NODESC 100000
#define N_EDGESC 2500000
#define IN_CH 32
#define HID 16
#define OUT_CH 64
#define NUM_GRAPHS 64

// ---------------- scratch ----------------
// f16 payload tables: 16 ch = 8 half2 = 32B/node
__device__ __align__(16) __half2 g_yh[N_NODESC * 8];     // f16(x @ w1_l^T)
__device__ __align__(16) __half2 g_h1h[N_NODESC * 8];    // f16(h1)
__device__ __align__(16) __half2 g_agg1h[N_NODESC * 8];  // f16 accumulators
__device__ __align__(16) __half2 g_agg2h[N_NODESC * 8];
__device__ __align__(16) float g_xr[N_NODESC * HID];     // x @ w1_r^T (fp32)
__device__ __align__(16) float g_cnt[N_NODESC];
__device__ __align__(16) float g_h1acc[NUM_GRAPHS * HID];
__device__ __align__(16) float g_m2acc[NUM_GRAPHS * HID];
__device__ __align__(16) float g_gcnt[NUM_GRAPHS];

__device__ __forceinline__ void red_add_v4f(float* p, float a, float b, float c, float d) {
    asm volatile("red.global.add.v4.f32 [%0], {%1, %2, %3, %4};"
                 :: "l"(p), "f"(a), "f"(b), "f"(c), "f"(d) : "memory");
}
__device__ __forceinline__ void red_add_v4h(__half2* p, uint32_t a, uint32_t b,
                                            uint32_t c, uint32_t d) {
    asm volatile("red.global.add.noftz.v4.f16x2 [%0], {%1, %2, %3, %4};"
                 :: "l"(p), "r"(a), "r"(b), "r"(c), "r"(d) : "memory");
}

// ---------------- Kernel 1: pre-transform; zero accumulators ----------------
__global__ void __launch_bounds__(256) kPre(const float* __restrict__ x,
                                            const float* __restrict__ w1l,
                                            const float* __restrict__ w1r) {
    __shared__ __align__(16) float swl[HID * IN_CH];
    __shared__ __align__(16) float swr[HID * IN_CH];
    int t = threadIdx.x;
    for (int i = t; i < HID * IN_CH; i += blockDim.x) {
        swl[i] = w1l[i];
        swr[i] = w1r[i];
    }
    __syncthreads();

    int n = blockIdx.x * blockDim.x + t;
    if (n >= N_NODESC) return;

    if (n < NUM_GRAPHS * HID) { g_h1acc[n] = 0.0f; g_m2acc[n] = 0.0f; }
    if (n < NUM_GRAPHS) g_gcnt[n] = 0.0f;

    float xv[IN_CH];
    const float4* xp = reinterpret_cast<const float4*>(x + (size_t)n * IN_CH);
#pragma unroll
    for (int i = 0; i < IN_CH / 4; i++) {
        float4 v = __ldg(xp + i);
        xv[4*i+0] = v.x; xv[4*i+1] = v.y; xv[4*i+2] = v.z; xv[4*i+3] = v.w;
    }

    float yl[HID], yr[HID];
#pragma unroll
    for (int o = 0; o < HID; o++) {
        float al = 0.0f, ar = 0.0f;
#pragma unroll
        for (int kk = 0; kk < IN_CH / 4; kk++) {
            float4 wl = *reinterpret_cast<float4*>(&swl[o * IN_CH + kk * 4]);
            float4 wr = *reinterpret_cast<float4*>(&swr[o * IN_CH + kk * 4]);
            al += xv[kk*4+0]*wl.x + xv[kk*4+1]*wl.y + xv[kk*4+2]*wl.z + xv[kk*4+3]*wl.w;
            ar += xv[kk*4+0]*wr.x + xv[kk*4+1]*wr.y + xv[kk*4+2]*wr.z + xv[kk*4+3]*wr.w;
        }
        yl[o] = al; yr[o] = ar;
    }

    // store y as f16 (8 half2 = 2 uint4)
    uint32_t yw[8];
#pragma unroll
    for (int i = 0; i < 8; i++) {
        __half2 h2 = __floats2half2_rn(yl[2*i], yl[2*i+1]);
        yw[i] = *reinterpret_cast<uint32_t*>(&h2);
    }
    uint4* yp = reinterpret_cast<uint4*>(g_yh + (size_t)n * 8);
    yp[0] = make_uint4(yw[0], yw[1], yw[2], yw[3]);
    yp[1] = make_uint4(yw[4], yw[5], yw[6], yw[7]);

    float4* rp = reinterpret_cast<float4*>(g_xr + (size_t)n * HID);
#pragma unroll
    for (int i = 0; i < HID / 4; i++)
        rp[i] = make_float4(yr[4*i], yr[4*i+1], yr[4*i+2], yr[4*i+3]);

    uint4* a1p = reinterpret_cast<uint4*>(g_agg1h + (size_t)n * 8);
    a1p[0] = make_uint4(0, 0, 0, 0);
    a1p[1] = make_uint4(0, 0, 0, 0);
    g_cnt[n] = 0.0f;
}

// ---------------- Kernel 2/4: f16 edge scatter, 2 threads/edge ----------------
template <int ADDCOUNT>
__global__ void __launch_bounds__(256) kScatterH(const int* __restrict__ ei,
                                                 const __half2* __restrict__ val,
                                                 __half2* __restrict__ acc) {
    int idx = blockIdx.x * blockDim.x + threadIdx.x;
    int e = idx >> 1;
    if (e >= N_EDGESC) return;
    int c = idx & 1;                    // 16B chunk within 32B row
    int s = __ldg(&ei[e]);
    int d = __ldg(&ei[N_EDGESC + e]);

    uint4 v = __ldg(reinterpret_cast<const uint4*>(val) + (size_t)s * 2 + c);
    red_add_v4h(acc + (size_t)d * 8 + c * 4, v.x, v.y, v.z, v.w);
    if (ADDCOUNT && c == 0) atomicAdd(&g_cnt[d], 1.0f);
}

// ---------------- Kernel 3: h1 = relu(mean(agg1)+b1+xr); store f16; readout fp32 ----------------
__global__ void __launch_bounds__(256) kLayer1R(const float* __restrict__ b1,
                                                const int* __restrict__ batch) {
    int n = blockIdx.x * blockDim.x + threadIdx.x;
    bool valid = n < N_NODESC;
    int nn = valid ? n : (N_NODESC - 1);
    int lane = threadIdx.x & 31;

    float inv = 1.0f / fmaxf(g_cnt[nn], 1.0f);
    const uint4* ap = reinterpret_cast<const uint4*>(g_agg1h + (size_t)nn * 8);
    uint4 a0 = ap[0], a1 = ap[1];
    uint32_t aw[8] = {a0.x, a0.y, a0.z, a0.w, a1.x, a1.y, a1.z, a1.w};

    float h[HID];
#pragma unroll
    for (int i = 0; i < 8; i++) {
        __half2 h2 = *reinterpret_cast<__half2*>(&aw[i]);
        float2 f = __half22float2(h2);
        h[2*i]   = f.x * inv;
        h[2*i+1] = f.y * inv;
    }
    const float4* rp = reinterpret_cast<const float4*>(g_xr + (size_t)nn * HID);
#pragma unroll
    for (int i = 0; i < 4; i++) {
        float4 r = rp[i];
        float4 bb = __ldg(reinterpret_cast<const float4*>(b1) + i);
        h[4*i+0] = fmaxf(h[4*i+0] + bb.x + r.x, 0.0f);
        h[4*i+1] = fmaxf(h[4*i+1] + bb.y + r.y, 0.0f);
        h[4*i+2] = fmaxf(h[4*i+2] + bb.z + r.z, 0.0f);
        h[4*i+3] = fmaxf(h[4*i+3] + bb.w + r.w, 0.0f);
    }

    if (valid) {
        // store h1 as f16 for the pass-2 scatter
        uint32_t hw[8];
#pragma unroll
        for (int i = 0; i < 8; i++) {
            __half2 h2 = __floats2half2_rn(h[2*i], h[2*i+1]);
            hw[i] = *reinterpret_cast<uint32_t*>(&h2);
        }
        uint4* hp = reinterpret_cast<uint4*>(g_h1h + (size_t)n * 8);
        hp[0] = make_uint4(hw[0], hw[1], hw[2], hw[3]);
        hp[1] = make_uint4(hw[4], hw[5], hw[6], hw[7]);
        // zero agg2
        uint4* a2p = reinterpret_cast<uint4*>(g_agg2h + (size_t)n * 8);
        a2p[0] = make_uint4(0, 0, 0, 0);
        a2p[1] = make_uint4(0, 0, 0, 0);
    } else {
#pragma unroll
        for (int o = 0; o < HID; o++) h[o] = 0.0f;
    }

    // ---- per-graph readout of fp32 h1 ----
    int g = __ldg(&batch[nn]);
    int g0 = __shfl_sync(0xffffffffu, g, 0);
    bool uni = __all_sync(0xffffffffu, g == g0);
    int nval = __popc(__ballot_sync(0xffffffffu, valid));

    if (uni) {
#pragma unroll
        for (int k = 0; k < HID; k++) {
            float v = h[k];
            v += __shfl_xor_sync(0xffffffffu, v, 16);
            v += __shfl_xor_sync(0xffffffffu, v, 8);
            v += __shfl_xor_sync(0xffffffffu, v, 4);
            v += __shfl_xor_sync(0xffffffffu, v, 2);
            v += __shfl_xor_sync(0xffffffffu, v, 1);
            h[k] = v;
        }
        if (lane == 0) {
            float* gp = g_h1acc + (size_t)g0 * HID;
#pragma unroll
            for (int k = 0; k < HID; k += 4)
                red_add_v4f(gp + k, h[k], h[k+1], h[k+2], h[k+3]);
            if (nval > 0) atomicAdd(&g_gcnt[g0], (float)nval);
        }
    } else if (valid) {
        float* gp = g_h1acc + (size_t)g * HID;
#pragma unroll
        for (int k = 0; k < HID; k += 4)
            red_add_v4f(gp + k, h[k], h[k+1], h[k+2], h[k+3]);
        atomicAdd(&g_gcnt[g], 1.0f);
    }
}

// ---------------- Kernel 5: m2 = mean(agg2); per-graph readout ----------------
__global__ void __launch_bounds__(256) kMean2R(const int* __restrict__ batch) {
    int n = blockIdx.x * blockDim.x + threadIdx.x;
    bool valid = n < N_NODESC;
    int nn = valid ? n : (N_NODESC - 1);
    int lane = threadIdx.x & 31;

    float inv = 1.0f / fmaxf(g_cnt[nn], 1.0f);
    const uint4* ap = reinterpret_cast<const uint4*>(g_agg2h + (size_t)nn * 8);
    uint4 a0 = ap[0], a1 = ap[1];
    uint32_t aw[8] = {a0.x, a0.y, a0.z, a0.w, a1.x, a1.y, a1.z, a1.w};

    float m[HID];
#pragma unroll
    for (int i = 0; i < 8; i++) {
        __half2 h2 = *reinterpret_cast<__half2*>(&aw[i]);
        float2 f = __half22float2(h2);
        m[2*i]   = valid ? f.x * inv : 0.0f;
        m[2*i+1] = valid ? f.y * inv : 0.0f;
    }

    int g = __ldg(&batch[nn]);
    int g0 = __shfl_sync(0xffffffffu, g, 0);
    bool uni = __all_sync(0xffffffffu, g == g0);

    if (uni) {
#pragma unroll
        for (int k = 0; k < HID; k++) {
            float v = m[k];
            v += __shfl_xor_sync(0xffffffffu, v, 16);
            v += __shfl_xor_sync(0xffffffffu, v, 8);
            v += __shfl_xor_sync(0xffffffffu, v, 4);
            v += __shfl_xor_sync(0xffffffffu, v, 2);
            v += __shfl_xor_sync(0xffffffffu, v, 1);
            m[k] = v;
        }
        if (lane == 0) {
            float* gp = g_m2acc + (size_t)g0 * HID;
#pragma unroll
            for (int k = 0; k < HID; k += 4)
                red_add_v4f(gp + k, m[k], m[k+1], m[k+2], m[k+3]);
        }
    } else if (valid) {
        float* gp = g_m2acc + (size_t)g * HID;
#pragma unroll
        for (int k = 0; k < HID; k += 4)
            red_add_v4f(gp + k, m[k], m[k+1], m[k+2], m[k+3]);
    }
}

// ---------------- Kernel 6: tiny output GEMM ----------------
__global__ void __launch_bounds__(256) kFinal(const float* __restrict__ w2l,
                                              const float* __restrict__ b2,
                                              const float* __restrict__ w2r,
                                              float* __restrict__ out) {
    int i = blockIdx.x * blockDim.x + threadIdx.x;
    if (i >= NUM_GRAPHS * OUT_CH) return;
    int g = i >> 6;
    int o = i & 63;

    float cnt = g_gcnt[g];
    if (cnt < 0.5f) { out[i] = 0.0f; return; }
    float inv = 1.0f / cnt;

    float sum = __ldg(&b2[o]);
#pragma unroll
    for (int k = 0; k < HID; k += 4) {
        float4 mm = *reinterpret_cast<const float4*>(&g_m2acc[g * HID + k]);
        float4 hh = *reinterpret_cast<const float4*>(&g_h1acc[g * HID + k]);
        float4 wl = __ldg(reinterpret_cast<const float4*>(w2l + o * HID + k));
        float4 wr = __ldg(reinterpret_cast<const float4*>(w2r + o * HID + k));
        sum += inv * (mm.x * wl.x + mm.y * wl.y + mm.z * wl.z + mm.w * wl.w
                    + hh.x * wr.x + hh.y * wr.y + hh.z * wr.z + hh.w * wr.w);
    }
    out[i] = sum;
}

// ---------------- launch ----------------
extern "C" void kernel_launch(void* const* d_in, const int* in_sizes, int n_in,
                              void* d_out, int out_size) {
    const float* x    = (const float*)d_in[0];
    const int*   ei   = (const int*)d_in[1];
    const int*   batch= (const int*)d_in[2];
    const float* w1l  = (const float*)d_in[3];
    const float* b1   = (const float*)d_in[4];
    const float* w1r  = (const float*)d_in[5];
    const float* w2l  = (const float*)d_in[6];
    const float* b2   = (const float*)d_in[7];
    const float* w2r  = (const float*)d_in[8];
    float* out = (float*)d_out;

    __half2* gy;  cudaGetSymbolAddress((void**)&gy,  g_yh);
    __half2* gh1; cudaGetSymbolAddress((void**)&gh1, g_h1h);
    __half2* ga1; cudaGetSymbolAddress((void**)&ga1, g_agg1h);
    __half2* ga2; cudaGetSymbolAddress((void**)&ga2, g_agg2h);

    const int TB = 256;
    int nodeBlocks = (N_NODESC + TB - 1) / TB;
    int pairBlocks = ((N_EDGESC * 2) + TB - 1) / TB;

    kPre<<<nodeBlocks, TB>>>(x, w1l, w1r);
    kScatterH<1><<<pairBlocks, TB>>>(ei, gy, ga1);
    kLayer1R<<<nodeBlocks, TB>>>(b1, batch);
    kScatterH<0><<<pairBlocks, TB>>>(ei, gh1, ga2);
    kMean2R<<<nodeBlocks, TB>>>(batch);
    kFinal<<<(NUM_GRAPHS * OUT_CH + TB - 1) / TB, TB>>>(w2l, b2, w2r, out);
}